// round 12
// baseline (speedup 1.0000x reference)
#include <cuda_runtime.h>
#include <math.h>
#include <stdint.h>

#define NN   100000
#define EE   400000
#define GG   2048
#define HH   256
#define H2   512
#define LLAY 5
#define AFEA 9
#define BFEA 3
#define AVOC 128
#define BVOC 16
#define BN_EPS 1e-5f

// Output layout (flattened float32), total 1,156,769 elements:
#define O_HS   0                      // head(sub)   [G,2]
#define O_HT   (2*GG)                 // head(triv)  [G,2]
#define O_SUB  (4*GG)                 // sub         [G,H]
#define O_GE   (4*GG + GG*HH)         // graph_emb   [G,H]
#define O_MASK (4*GG + 2*GG*HH)       // active_mask [N]
#define O_PEN  (4*GG + 2*GG*HH + NN)  // con_penalty scalar

// ---------------- scratch (device globals; no allocs allowed) ----------------
__device__ float g_h[(size_t)NN * HH];
__device__ float g_agg[(size_t)NN * HH];
__device__ float g_z[(size_t)NN * H2];
__device__ float g_assign[(size_t)NN * 2];
__device__ float g_sub[GG * HH];
__device__ float g_triv[GG * HH];
__device__ float g_gsum[GG * HH];
__device__ float g_cnt[GG];
__device__ float g_adj[GG * 4];
__device__ float g_pen[1];

// Pre-split tf32 weights, [K][N] layout, hi/lo INTERLEAVED: word 2*idx = hi, 2*idx+1 = lo.
#define WOFF_W1(l) ((size_t)(l) * 131072)
#define WOFF_W2(l) (655360 + (size_t)(l) * 131072)
#define WOFF_C1   1310720
#define WTOT      1376256
__device__ uint32_t g_wi[2 * WTOT];

// ---------------- small utilities ----------------
__device__ __forceinline__ float2 block_reduce2(float a, float b) {
    __shared__ float s0[8], s1[8];
    __shared__ float r0, r1;
    int wid = threadIdx.x >> 5, lane = threadIdx.x & 31;
#pragma unroll
    for (int o = 16; o > 0; o >>= 1) {
        a += __shfl_down_sync(0xffffffffu, a, o);
        b += __shfl_down_sync(0xffffffffu, b, o);
    }
    if (lane == 0) { s0[wid] = a; s1[wid] = b; }
    __syncthreads();
    if (wid == 0) {
        a = (lane < 8) ? s0[lane] : 0.f;
        b = (lane < 8) ? s1[lane] : 0.f;
#pragma unroll
        for (int o = 4; o > 0; o >>= 1) {
            a += __shfl_down_sync(0xffffffffu, a, o);
            b += __shfl_down_sync(0xffffffffu, b, o);
        }
        if (lane == 0) { r0 = a; r1 = b; }
    }
    __syncthreads();
    return make_float2(r0, r1);
}

__device__ __forceinline__ uint32_t f2tf32(float x) {
    uint32_t r;
    asm("cvt.rna.tf32.f32 %0, %1;" : "=r"(r) : "f"(x));
    return r;
}

__device__ __forceinline__ uint32_t smem_u32(const void* p) {
    uint32_t a;
    asm("{ .reg .u64 t; cvta.to.shared.u64 t, %1; cvt.u32.u64 %0, t; }" : "=r"(a) : "l"(p));
    return a;
}

__device__ __forceinline__ void cp_async16(uint32_t dst, const void* src) {
    asm volatile("cp.async.ca.shared.global [%0], [%1], 16;" :: "r"(dst), "l"(src) : "memory");
}
#define CP_COMMIT() asm volatile("cp.async.commit_group;" ::: "memory")
#define CP_WAIT0()  asm volatile("cp.async.wait_group 0;" ::: "memory")

__device__ __forceinline__ void mma_tf32(float* d, const uint32_t* a, uint32_t b0, uint32_t b1) {
    asm volatile("mma.sync.aligned.m16n8k8.row.col.f32.tf32.tf32.f32 "
                 "{%0,%1,%2,%3}, {%4,%5,%6,%7}, {%8,%9}, {%0,%1,%2,%3};"
                 : "+f"(d[0]), "+f"(d[1]), "+f"(d[2]), "+f"(d[3])
                 : "r"(a[0]), "r"(a[1]), "r"(a[2]), "r"(a[3]), "r"(b0), "r"(b1));
}

__device__ __forceinline__ void red_add_v4(float* p, float a, float b, float c, float d) {
    asm volatile("red.global.add.v4.f32 [%0], {%1, %2, %3, %4};"
                 :: "l"(p), "f"(a), "f"(b), "f"(c), "f"(d) : "memory");
}

// ---------------- misc kernels ----------------

__global__ __launch_bounds__(256) void zero_k() {
    int i = blockIdx.x * 256 + threadIdx.x;
    if (i < GG * HH) { g_sub[i] = 0.f; g_triv[i] = 0.f; g_gsum[i] = 0.f; }
    if (i < GG)       g_cnt[i] = 0.f;
    if (i < GG * 4)   g_adj[i] = 0.f;
    if (i == 0)       g_pen[0] = 0.f;
}

// Split W[K][N] into interleaved tf32 hi/lo words at dw ([K][N][2]).
__global__ __launch_bounds__(256) void wsplit(const float* __restrict__ W,
                                              uint32_t* __restrict__ dw,
                                              int N) {
    int n = blockIdx.x * 256 + threadIdx.x;
    int k = blockIdx.y;
    if (n >= N) return;
    size_t idx = (size_t)k * N + n;
    float v = W[idx];
    uint32_t h = f2tf32(v);
    uint2 o = make_uint2(h, f2tf32(v - __uint_as_float(h)));
    *reinterpret_cast<uint2*>(dw + idx * 2) = o;
}

__global__ __launch_bounds__(256) void atom_enc(const int* __restrict__ x,
                                                const float* __restrict__ aemb,
                                                const float* __restrict__ eps) {
    int n = blockIdx.x;
    int c = threadIdx.x;
    __shared__ int xs[AFEA];
    if (threadIdx.x < AFEA) xs[threadIdx.x] = x[n * AFEA + threadIdx.x];
    __syncthreads();
    float s = 0.f;
#pragma unroll
    for (int f = 0; f < AFEA; f++)
        s += aemb[((size_t)f * AVOC + xs[f]) * HH + c];
    g_h[(size_t)n * HH + c] = s;
    g_agg[(size_t)n * HH + c] = (1.f + eps[0]) * s;
}

// per-edge: agg[dst] += relu(h[src] + e_emb);  vector reductions (red.v4)
__global__ __launch_bounds__(256) void edge_msg(const int* __restrict__ ei,
                                                const int* __restrict__ ea,
                                                const float* __restrict__ bemb) {
    int e = blockIdx.x * 8 + (threadIdx.x >> 5);
    if (e >= EE) return;
    int lane = threadIdx.x & 31;
    int src = ei[e], dst = ei[EE + e];
    int a0 = ea[e * 3 + 0], a1 = ea[e * 3 + 1], a2 = ea[e * 3 + 2];
    const float* b0 = bemb + (size_t)(0 * BVOC + a0) * HH;
    const float* b1 = bemb + (size_t)(1 * BVOC + a1) * HH;
    const float* b2 = bemb + (size_t)(2 * BVOC + a2) * HH;
    const float* hs = g_h + (size_t)src * HH;
    float* ag = g_agg + (size_t)dst * HH;
#pragma unroll
    for (int v = 0; v < 2; v++) {
        int c = v * 128 + lane * 4;
        float4 hv = *reinterpret_cast<const float4*>(hs + c);
        float4 e0 = *reinterpret_cast<const float4*>(b0 + c);
        float4 e1 = *reinterpret_cast<const float4*>(b1 + c);
        float4 e2 = *reinterpret_cast<const float4*>(b2 + c);
        float m0 = fmaxf(hv.x + e0.x + e1.x + e2.x, 0.f);
        float m1 = fmaxf(hv.y + e0.y + e1.y + e2.y, 0.f);
        float m2 = fmaxf(hv.z + e0.z + e1.z + e2.z, 0.f);
        float m3 = fmaxf(hv.w + e0.w + e1.w + e2.w, 0.f);
        red_add_v4(ag + c, m0, m1, m2, m3);
    }
}

// ---------------------------------------------------------------------------
// 3xTF32 mma.sync GEMM, hi/lo-interleaved smem (LDS.64 fragment loads).
// C[M,Nc] = A[M,K] @ W[K,Nc]; W pre-split interleaved [K][N][2] (g_wi).
// Block tile 128x128, BK=8, 8 warps (4m x 2n), warp tile 32x64.
// A smem: [row][c*2 + {h,l}], stride 24 words/row (conflict-free LDS.64).
// B smem: [k][n*2 + {h,l}], stride 280 words/k-row (conflict-free LDS.64).
// Epilogues: 0 BN+ReLU, 1 +bias (+optional agg_out scale), 2 tanh(+bias)
// ---------------------------------------------------------------------------
#define ASTR 24
#define BSTR 280
__global__ __launch_bounds__(256) void mma_gemm(
    const float* __restrict__ A, const uint32_t* __restrict__ BG,
    float* __restrict__ C,
    int M, int K, int Nc, int mode,
    const float* __restrict__ bias,
    const float* __restrict__ gamma, const float* __restrict__ beta,
    const float* __restrict__ mean, const float* __restrict__ var,
    const float* __restrict__ eps, int next_l, float* __restrict__ agg_out) {
    __shared__ uint32_t As[2][128 * ASTR];   // 24 KB
    __shared__ uint32_t Bs[2][8 * BSTR];     // 17.5 KB

    const int tid = threadIdx.x;
    const int m0 = blockIdx.x * 128, n0 = blockIdx.y * 128;
    const int lane = tid & 31, wid = tid >> 5;
    const int wm = (wid & 3) * 32;
    const int wn = (wid >> 2) * 64;
    const int g = lane >> 2, ct = lane & 3;

    // A staging: 2 threads/row, 4 consecutive c each
    const int arow = tid >> 1, aco = (tid & 1) << 2;
    const int grow = m0 + arow;
    const bool aval = grow < M;
    const float* Aptr = A + (size_t)grow * K + aco;
    // B staging: 32 threads/k-row, 8 words (4 n-values) each
    const int brow = tid >> 5, bwo = (tid & 31) << 3;   // word offset in [k][2N] row
    const uint32_t* Bptr = BG + ((size_t)brow * Nc + n0) * 2 + bwo;

    // ---- tile 0 ----
    cp_async16(smem_u32(&Bs[0][brow * BSTR + bwo]), Bptr);
    cp_async16(smem_u32(&Bs[0][brow * BSTR + bwo + 4]), Bptr + 4);
    CP_COMMIT();
    float4 ap = aval ? *reinterpret_cast<const float4*>(Aptr)
                     : make_float4(0.f, 0.f, 0.f, 0.f);
    {
        float av[4] = {ap.x, ap.y, ap.z, ap.w};
#pragma unroll
        for (int j = 0; j < 4; j++) {
            uint32_t hi = f2tf32(av[j]);
            uint2 o = make_uint2(hi, f2tf32(av[j] - __uint_as_float(hi)));
            *reinterpret_cast<uint2*>(&As[0][arow * ASTR + (aco + j) * 2]) = o;
        }
    }
    CP_WAIT0();
    __syncthreads();

    float acc[2][8][4];
#pragma unroll
    for (int mi = 0; mi < 2; mi++)
#pragma unroll
        for (int ni = 0; ni < 8; ni++)
#pragma unroll
            for (int q = 0; q < 4; q++) acc[mi][ni][q] = 0.f;

    const int nk = K >> 3;
    int buf = 0;
    for (int kt = 0; kt < nk; kt++) {
        const int nb = buf ^ 1;
        if (kt + 1 < nk) {
            int kb = (kt + 1) << 3;
            const uint32_t* bp = Bptr + (size_t)kb * Nc * 2;
            cp_async16(smem_u32(&Bs[nb][brow * BSTR + bwo]), bp);
            cp_async16(smem_u32(&Bs[nb][brow * BSTR + bwo + 4]), bp + 4);
            CP_COMMIT();
            ap = aval ? *reinterpret_cast<const float4*>(Aptr + kb)
                      : make_float4(0.f, 0.f, 0.f, 0.f);
        }
        // A fragments: LDS.64 gives {hi, lo}
        uint32_t ah[2][4], al[2][4];
#pragma unroll
        for (int mi = 0; mi < 2; mi++) {
            int mbase = wm + mi * 16;
#pragma unroll
            for (int q = 0; q < 4; q++) {
                int r = mbase + g + (q & 1) * 8;
                int c = ct + (q >> 1) * 4;
                uint2 v = *reinterpret_cast<const uint2*>(&As[buf][r * ASTR + c * 2]);
                ah[mi][q] = v.x;
                al[mi][q] = v.y;
            }
        }
#pragma unroll
        for (int ni = 0; ni < 8; ni++) {
            int nbase = (wn + ni * 8 + g) * 2;
            uint2 v0 = *reinterpret_cast<const uint2*>(&Bs[buf][ct * BSTR + nbase]);
            uint2 v1 = *reinterpret_cast<const uint2*>(&Bs[buf][(ct + 4) * BSTR + nbase]);
#pragma unroll
            for (int mi = 0; mi < 2; mi++) {
                mma_tf32(acc[mi][ni], ah[mi], v0.y, v1.y);   // Ah*Bl
                mma_tf32(acc[mi][ni], al[mi], v0.x, v1.x);   // Al*Bh
                mma_tf32(acc[mi][ni], ah[mi], v0.x, v1.x);   // Ah*Bh
            }
        }
        if (kt + 1 < nk) {
            float av[4] = {ap.x, ap.y, ap.z, ap.w};
#pragma unroll
            for (int j = 0; j < 4; j++) {
                uint32_t hi = f2tf32(av[j]);
                uint2 o = make_uint2(hi, f2tf32(av[j] - __uint_as_float(hi)));
                *reinterpret_cast<uint2*>(&As[nb][arow * ASTR + (aco + j) * 2]) = o;
            }
            CP_WAIT0();
        }
        __syncthreads();
        buf ^= 1;
    }

    // epilogue (fragment layout identical to R5/R10)
    float aggsc = 0.f;
    if (agg_out) aggsc = 1.f + __ldg(eps + next_l);
#pragma unroll
    for (int mi = 0; mi < 2; mi++) {
#pragma unroll
        for (int half = 0; half < 2; half++) {
            int r = m0 + wm + mi * 16 + g + half * 8;
            if (r >= M) continue;
#pragma unroll
            for (int ni = 0; ni < 8; ni++) {
                int cix = n0 + wn + ni * 8 + ct * 2;
                float v0 = acc[mi][ni][half * 2 + 0];
                float v1 = acc[mi][ni][half * 2 + 1];
                if (mode == 0) {
                    float sc0 = gamma[cix + 0] * rsqrtf(var[cix + 0] + BN_EPS);
                    float sc1 = gamma[cix + 1] * rsqrtf(var[cix + 1] + BN_EPS);
                    v0 = fmaxf((v0 + bias[cix + 0] - mean[cix + 0]) * sc0 + beta[cix + 0], 0.f);
                    v1 = fmaxf((v1 + bias[cix + 1] - mean[cix + 1]) * sc1 + beta[cix + 1], 0.f);
                } else if (mode == 1) {
                    v0 += bias[cix + 0];
                    v1 += bias[cix + 1];
                } else {
                    v0 = tanhf(v0 + bias[cix + 0]);
                    v1 = tanhf(v1 + bias[cix + 1]);
                }
                *reinterpret_cast<float2*>(C + (size_t)r * Nc + cix) = make_float2(v0, v1);
                if (agg_out) {
                    *reinterpret_cast<float2*>(agg_out + (size_t)r * Nc + cix) =
                        make_float2(v0 * aggsc, v1 * aggsc);
                }
            }
        }
    }
}

// ---------------- remaining pipeline (unchanged, proven) ----------------

__global__ __launch_bounds__(256) void assign_pool(const float* __restrict__ c2W,
                                                   const float* __restrict__ c2b,
                                                   const int* __restrict__ batch,
                                                   float* __restrict__ out) {
    int n = blockIdx.x;
    int c = threadIdx.x;
    float t = g_agg[(size_t)n * HH + c];
    float2 lg = block_reduce2(t * c2W[c * 2 + 0], t * c2W[c * 2 + 1]);
    float l0 = lg.x + c2b[0], l1 = lg.y + c2b[1];
    float m = fmaxf(l0, l1);
    float e0 = expf(l0 - m), e1 = expf(l1 - m);
    float inv = 1.f / (e0 + e1);
    float a0 = e0 * inv, a1 = e1 * inv;
    float hv = g_h[(size_t)n * HH + c];
    int g = batch[n];
    atomicAdd(&g_sub[g * HH + c], a0 * hv);
    atomicAdd(&g_triv[g * HH + c], a1 * hv);
    atomicAdd(&g_gsum[g * HH + c], hv);
    if (c == 0) {
        atomicAdd(&g_cnt[g], 1.f);
        out[O_MASK + n] = (a0 > 0.5f) ? 1.f : 0.f;
        g_assign[(size_t)n * 2 + 0] = a0;
        g_assign[(size_t)n * 2 + 1] = a1;
    }
}

__global__ __launch_bounds__(256) void adj_k(const int* __restrict__ ei,
                                             const int* __restrict__ batch) {
    int e = blockIdx.x * 256 + threadIdx.x;
    if (e >= EE) return;
    int s = ei[e], d = ei[EE + e];
    int gs = batch[s], gd = batch[d];
    if (gs != gd) return;
    float as0 = g_assign[(size_t)s * 2], as1 = g_assign[(size_t)s * 2 + 1];
    float ad0 = g_assign[(size_t)d * 2], ad1 = g_assign[(size_t)d * 2 + 1];
    float* A = g_adj + gs * 4;
    atomicAdd(A + 0, as0 * ad0);
    atomicAdd(A + 1, as0 * ad1);
    atomicAdd(A + 2, as1 * ad0);
    atomicAdd(A + 3, as1 * ad1);
}

__global__ __launch_bounds__(256) void fin_pool(float* __restrict__ out) {
    int i = blockIdx.x * 256 + threadIdx.x;
    if (i >= GG * HH) return;
    int g = i / HH;
    out[O_SUB + i] = g_sub[i];
    out[O_GE + i] = g_gsum[i] / fmaxf(g_cnt[g], 1.f);
}

__global__ __launch_bounds__(256) void head_k(int which,
                                              const float* __restrict__ l1W,
                                              const float* __restrict__ l1b,
                                              const float* __restrict__ l2W,
                                              const float* __restrict__ l2b,
                                              float* __restrict__ out) {
    int g = blockIdx.x;
    int c = threadIdx.x;
    __shared__ float row[HH];
    row[c] = (which == 0) ? g_sub[(size_t)g * HH + c] : g_triv[(size_t)g * HH + c];
    __syncthreads();
    float acc = l1b[c];
#pragma unroll 4
    for (int k = 0; k < HH; k++)
        acc += row[k] * l1W[(size_t)k * HH + c];
    float z = fmaxf(acc, 0.f);
    float2 lg = block_reduce2(z * l2W[c * 2 + 0], z * l2W[c * 2 + 1]);
    if (c == 0) {
        float l0 = lg.x + l2b[0], l1 = lg.y + l2b[1];
        float m = fmaxf(l0, l1);
        float ls = logf(expf(l0 - m) + expf(l1 - m)) + m;
        out[g * 2 + 0] = l0 - ls;
        out[g * 2 + 1] = l1 - ls;
    }
}

__global__ __launch_bounds__(256) void pen_k() {
    int g = blockIdx.x * 256 + threadIdx.x;
    if (g >= GG) return;
    float a00 = g_adj[g * 4 + 0], a01 = g_adj[g * 4 + 1];
    float a10 = g_adj[g * 4 + 2], a11 = g_adj[g * 4 + 3];
    float r0 = fmaxf(fabsf(a00) + fabsf(a01), 1e-12f);
    float r1 = fmaxf(fabsf(a10) + fabsf(a11), 1e-12f);
    float d0 = a00 / r0 - 1.f, d1 = a11 / r1 - 1.f;
    atomicAdd(g_pen, d0 * d0 + d1 * d1);
}

__global__ void pen_w(float* __restrict__ out) {
    out[O_PEN] = g_pen[0] / (2.f * GG);
}

// ---------------- host launcher ----------------
extern "C" void kernel_launch(void* const* d_in, const int* in_sizes, int n_in,
                              void* d_out, int out_size) {
    int o = (n_in >= 24) ? 1 : 0;
    const int*   x     = (const int*)d_in[0];
    const int*   ei    = (const int*)d_in[1];
    const int*   ea    = (const int*)d_in[2];
    const int*   batch = (const int*)d_in[3];
    const float* aemb  = (const float*)d_in[4 + o];
    const float* bemb  = (const float*)d_in[5 + o];
    const float* eps   = (const float*)d_in[6 + o];
    const float* W1    = (const float*)d_in[7 + o];
    const float* b1    = (const float*)d_in[8 + o];
    const float* gma   = (const float*)d_in[9 + o];
    const float* bta   = (const float*)d_in[10 + o];
    const float* mu    = (const float*)d_in[11 + o];
    const float* var   = (const float*)d_in[12 + o];
    const float* W2    = (const float*)d_in[13 + o];
    const float* b2    = (const float*)d_in[14 + o];
    const float* c1W   = (const float*)d_in[15 + o];
    const float* c1b   = (const float*)d_in[16 + o];
    const float* c2W   = (const float*)d_in[17 + o];
    const float* c2b   = (const float*)d_in[18 + o];
    const float* l1W   = (const float*)d_in[19 + o];
    const float* l1b   = (const float*)d_in[20 + o];
    const float* l2W   = (const float*)d_in[21 + o];
    const float* l2b   = (const float*)d_in[22 + o];
    float* out = (float*)d_out;

    float *p_h, *p_agg, *p_z;
    uint32_t *p_wi;
    cudaGetSymbolAddress((void**)&p_h, g_h);
    cudaGetSymbolAddress((void**)&p_agg, g_agg);
    cudaGetSymbolAddress((void**)&p_z, g_z);
    cudaGetSymbolAddress((void**)&p_wi, g_wi);

    zero_k<<<(GG * HH + 255) / 256, 256>>>();
    atom_enc<<<NN, 256>>>(x, aemb, eps);

    // pre-split weights (static per launch): W[K][N] -> interleaved tf32 hi/lo
    for (int l = 0; l < LLAY; l++) {
        wsplit<<<dim3(2, HH), 256>>>(W1 + (size_t)l * HH * H2,
                                     p_wi + 2 * WOFF_W1(l), H2);
        wsplit<<<dim3(1, H2), 256>>>(W2 + (size_t)l * H2 * HH,
                                     p_wi + 2 * WOFF_W2(l), HH);
    }
    wsplit<<<dim3(1, HH), 256>>>(c1W, p_wi + 2 * WOFF_C1, HH);

    const int gmx = (NN + 127) / 128;
    for (int l = 0; l < LLAY; l++) {
        edge_msg<<<(EE + 7) / 8, 256>>>(ei, ea, bemb + (size_t)l * BFEA * BVOC * HH);
        // z = relu(BN(agg @ W1[l] + b1[l]))   [N, 512]
        mma_gemm<<<dim3(gmx, H2 / 128), 256>>>(p_agg,
                                               p_wi + 2 * WOFF_W1(l),
                                               p_z, NN, HH, H2, 0,
                                               b1 + (size_t)l * H2, gma + (size_t)l * H2,
                                               bta + (size_t)l * H2, mu + (size_t)l * H2,
                                               var + (size_t)l * H2,
                                               nullptr, 0, nullptr);
        // h = z @ W2[l] + b2[l]               [N, 256]; fused agg init for next layer
        float* next_agg = (l + 1 < LLAY) ? p_agg : nullptr;
        mma_gemm<<<dim3(gmx, HH / 128), 256>>>(p_z,
                                               p_wi + 2 * WOFF_W2(l),
                                               p_h, NN, H2, HH, 1,
                                               b2 + (size_t)l * HH, nullptr, nullptr,
                                               nullptr, nullptr,
                                               eps, l + 1, next_agg);
    }

    // t = tanh(h @ c1W + c1b)  -> g_agg
    mma_gemm<<<dim3(gmx, HH / 128), 256>>>(p_h,
                                           p_wi + 2 * WOFF_C1,
                                           p_agg, NN, HH, HH, 2,
                                           c1b, nullptr, nullptr, nullptr, nullptr,
                                           nullptr, 0, nullptr);

    assign_pool<<<NN, 256>>>(c2W, c2b, batch, out);
    adj_k<<<(EE + 255) / 256, 256>>>(ei, batch);
    fin_pool<<<(GG * HH + 255) / 256, 256>>>(out);
    head_k<<<GG, 256>>>(0, l1W, l1b, l2W, l2b, out + O_HS);
    head_k<<<GG, 256>>>(1, l1W, l1b, l2W, l2b, out + O_HT);
    pen_k<<<(GG + 255) / 256, 256>>>();
    pen_w<<<1, 1>>>(out);
    (void)in_sizes; (void)out_size;
}

// round 13
// speedup vs baseline: 1.0249x; 1.0249x over previous
#include <cuda_runtime.h>
#include <math.h>
#include <stdint.h>

#define NN   100000
#define EE   400000
#define GG   2048
#define HH   256
#define H2   512
#define LLAY 5
#define AFEA 9
#define BFEA 3
#define AVOC 128
#define BVOC 16
#define BN_EPS 1e-5f

// Output layout (flattened float32), total 1,156,769 elements:
#define O_HS   0                      // head(sub)   [G,2]
#define O_HT   (2*GG)                 // head(triv)  [G,2]
#define O_SUB  (4*GG)                 // sub         [G,H]
#define O_GE   (4*GG + GG*HH)         // graph_emb   [G,H]
#define O_MASK (4*GG + 2*GG*HH)       // active_mask [N]
#define O_PEN  (4*GG + 2*GG*HH + NN)  // con_penalty scalar

// ---------------- scratch (device globals; no allocs allowed) ----------------
__device__ float g_h[(size_t)NN * HH];
__device__ float g_agg[(size_t)NN * HH];
__device__ float g_z[(size_t)NN * H2];
__device__ float g_assign[(size_t)NN * 2];
__device__ float g_sub[GG * HH];
__device__ float g_triv[GG * HH];
__device__ float g_gsum[GG * HH];
__device__ float g_cnt[GG];
__device__ float g_adj[GG * 4];
__device__ float g_pen[1];

// Pre-split tf32 hi/lo weights, SAME [K][N] layout as the source weights.
#define WOFF_W1(l) ((size_t)(l) * 131072)
#define WOFF_W2(l) (655360 + (size_t)(l) * 131072)
#define WOFF_C1   1310720
#define WTOT      1376256
__device__ uint32_t g_wh[WTOT];
__device__ uint32_t g_wl[WTOT];

// Precomputed bond-embedding sums: bsum[l][a0][a1][a2][c], 5*16^3*256 floats (21MB)
#define NCOMBO 4096
__device__ float g_bsum[(size_t)LLAY * NCOMBO * HH];

// ---------------- small utilities ----------------
__device__ __forceinline__ float2 block_reduce2(float a, float b) {
    __shared__ float s0[8], s1[8];
    __shared__ float r0, r1;
    int wid = threadIdx.x >> 5, lane = threadIdx.x & 31;
#pragma unroll
    for (int o = 16; o > 0; o >>= 1) {
        a += __shfl_down_sync(0xffffffffu, a, o);
        b += __shfl_down_sync(0xffffffffu, b, o);
    }
    if (lane == 0) { s0[wid] = a; s1[wid] = b; }
    __syncthreads();
    if (wid == 0) {
        a = (lane < 8) ? s0[lane] : 0.f;
        b = (lane < 8) ? s1[lane] : 0.f;
#pragma unroll
        for (int o = 4; o > 0; o >>= 1) {
            a += __shfl_down_sync(0xffffffffu, a, o);
            b += __shfl_down_sync(0xffffffffu, b, o);
        }
        if (lane == 0) { r0 = a; r1 = b; }
    }
    __syncthreads();
    return make_float2(r0, r1);
}

__device__ __forceinline__ uint32_t f2tf32(float x) {
    uint32_t r;
    asm("cvt.rna.tf32.f32 %0, %1;" : "=r"(r) : "f"(x));
    return r;
}

__device__ __forceinline__ uint32_t smem_u32(const void* p) {
    uint32_t a;
    asm("{ .reg .u64 t; cvta.to.shared.u64 t, %1; cvt.u32.u64 %0, t; }" : "=r"(a) : "l"(p));
    return a;
}

__device__ __forceinline__ void cp_async16(uint32_t dst, const void* src) {
    asm volatile("cp.async.ca.shared.global [%0], [%1], 16;" :: "r"(dst), "l"(src) : "memory");
}
#define CP_COMMIT() asm volatile("cp.async.commit_group;" ::: "memory")
#define CP_WAIT0()  asm volatile("cp.async.wait_group 0;" ::: "memory")

__device__ __forceinline__ void mma_tf32(float* d, const uint32_t* a, uint32_t b0, uint32_t b1) {
    asm volatile("mma.sync.aligned.m16n8k8.row.col.f32.tf32.tf32.f32 "
                 "{%0,%1,%2,%3}, {%4,%5,%6,%7}, {%8,%9}, {%0,%1,%2,%3};"
                 : "+f"(d[0]), "+f"(d[1]), "+f"(d[2]), "+f"(d[3])
                 : "r"(a[0]), "r"(a[1]), "r"(a[2]), "r"(a[3]), "r"(b0), "r"(b1));
}

// ---------------- misc kernels ----------------

__global__ __launch_bounds__(256) void zero_k() {
    int i = blockIdx.x * 256 + threadIdx.x;
    if (i < GG * HH) { g_sub[i] = 0.f; g_triv[i] = 0.f; g_gsum[i] = 0.f; }
    if (i < GG)       g_cnt[i] = 0.f;
    if (i < GG * 4)   g_adj[i] = 0.f;
    if (i == 0)       g_pen[0] = 0.f;
}

// Split W[K][N] (row-major) into tf32 hi/lo word arrays, SAME [K][N] layout.
__global__ __launch_bounds__(256) void wsplit(const float* __restrict__ W,
                                              uint32_t* __restrict__ dh,
                                              uint32_t* __restrict__ dl,
                                              int N) {
    int n = blockIdx.x * 256 + threadIdx.x;
    int k = blockIdx.y;
    if (n >= N) return;
    size_t idx = (size_t)k * N + n;
    float v = W[idx];
    uint32_t h = f2tf32(v);
    dh[idx] = h;
    dl[idx] = f2tf32(v - __uint_as_float(h));
}

// Precompute bsum[l][a0][a1][a2][c] = bond_emb[l,0,a0,c]+bond_emb[l,1,a1,c]+bond_emb[l,2,a2,c]
__global__ __launch_bounds__(256) void bsum_k(const float* __restrict__ bemb) {
    int combo = blockIdx.x;       // 0..4095
    int l = blockIdx.y;           // 0..4
    int c = threadIdx.x;
    int a0 = combo >> 8, a1 = (combo >> 4) & 15, a2 = combo & 15;
    const float* base = bemb + (size_t)l * BFEA * BVOC * HH;
    float v = base[(size_t)(0 * BVOC + a0) * HH + c]
            + base[(size_t)(1 * BVOC + a1) * HH + c]
            + base[(size_t)(2 * BVOC + a2) * HH + c];
    g_bsum[((size_t)l * NCOMBO + combo) * HH + c] = v;
}

__global__ __launch_bounds__(256) void atom_enc(const int* __restrict__ x,
                                                const float* __restrict__ aemb,
                                                const float* __restrict__ eps) {
    int n = blockIdx.x;
    int c = threadIdx.x;
    __shared__ int xs[AFEA];
    if (threadIdx.x < AFEA) xs[threadIdx.x] = x[n * AFEA + threadIdx.x];
    __syncthreads();
    float s = 0.f;
#pragma unroll
    for (int f = 0; f < AFEA; f++)
        s += aemb[((size_t)f * AVOC + xs[f]) * HH + c];
    g_h[(size_t)n * HH + c] = s;
    g_agg[(size_t)n * HH + c] = (1.f + eps[0]) * s;
}

// per-edge: agg[dst] += relu(h[src] + bsum[combo]);  1 warp per edge
__global__ __launch_bounds__(256) void edge_msg(const int* __restrict__ ei,
                                                const int* __restrict__ ea,
                                                int l) {
    int e = blockIdx.x * 8 + (threadIdx.x >> 5);
    if (e >= EE) return;
    int lane = threadIdx.x & 31;
    int src = ei[e], dst = ei[EE + e];
    int a0 = ea[e * 3 + 0], a1 = ea[e * 3 + 1], a2 = ea[e * 3 + 2];
    int combo = (a0 << 8) | (a1 << 4) | a2;
    const float* bs = g_bsum + ((size_t)l * NCOMBO + combo) * HH;
    const float* hs = g_h + (size_t)src * HH;
    float* ag = g_agg + (size_t)dst * HH;
#pragma unroll
    for (int v = 0; v < 2; v++) {
        int c = v * 128 + lane * 4;
        float4 hv = *reinterpret_cast<const float4*>(hs + c);
        float4 ev = *reinterpret_cast<const float4*>(bs + c);
        float m0 = fmaxf(hv.x + ev.x, 0.f);
        float m1 = fmaxf(hv.y + ev.y, 0.f);
        float m2 = fmaxf(hv.z + ev.z, 0.f);
        float m3 = fmaxf(hv.w + ev.w, 0.f);
        atomicAdd(ag + c + 0, m0);
        atomicAdd(ag + c + 1, m1);
        atomicAdd(ag + c + 2, m2);
        atomicAdd(ag + c + 3, m3);
    }
}

// ---------------------------------------------------------------------------
// 3xTF32 mma.sync GEMM (R10, proven): C[M,Nc] = A[M,K] @ W[K,Nc].
// W pre-split into tf32 hi/lo [K][N]; B staged via cp.async into Bs[k][n]
// stride-136 smem. A split in registers. 128x128 tile, BK=8, 8 warps.
// ---------------------------------------------------------------------------
#define ASTR 12
#define BSTR 136
__global__ __launch_bounds__(256) void mma_gemm(
    const float* __restrict__ A, const uint32_t* __restrict__ BhG,
    const uint32_t* __restrict__ BlG, float* __restrict__ C,
    int M, int K, int Nc, int mode,
    const float* __restrict__ bias,
    const float* __restrict__ gamma, const float* __restrict__ beta,
    const float* __restrict__ mean, const float* __restrict__ var,
    const float* __restrict__ eps, int next_l, float* __restrict__ agg_out) {
    __shared__ uint32_t As_h[2][128 * ASTR];
    __shared__ uint32_t As_l[2][128 * ASTR];
    __shared__ uint32_t Bs_h[2][8 * BSTR];
    __shared__ uint32_t Bs_l[2][8 * BSTR];

    const int tid = threadIdx.x;
    const int m0 = blockIdx.x * 128, n0 = blockIdx.y * 128;
    const int lane = tid & 31, wid = tid >> 5;
    const int wm = (wid & 3) * 32;
    const int wn = (wid >> 2) * 64;
    const int g = lane >> 2, ct = lane & 3;

    const int arow = tid >> 1, acol = (tid & 1) << 2;     // A: 128 x 8
    const int brow = tid >> 5, bcol = (tid & 31) << 2;    // B: 8 x 128
    const int grow = m0 + arow;
    const bool aval = grow < M;
    const float* Aptr = A + (size_t)grow * K + acol;
    const uint32_t* BptrH = BhG + (size_t)brow * Nc + n0 + bcol;
    const uint32_t* BptrL = BlG + (size_t)brow * Nc + n0 + bcol;

    cp_async16(smem_u32(&Bs_h[0][brow * BSTR + bcol]), BptrH);
    cp_async16(smem_u32(&Bs_l[0][brow * BSTR + bcol]), BptrL);
    CP_COMMIT();
    float4 ap = aval ? *reinterpret_cast<const float4*>(Aptr)
                     : make_float4(0.f, 0.f, 0.f, 0.f);
    {
        float av[4] = {ap.x, ap.y, ap.z, ap.w};
#pragma unroll
        for (int j = 0; j < 4; j++) {
            uint32_t hi = f2tf32(av[j]);
            As_h[0][arow * ASTR + acol + j] = hi;
            As_l[0][arow * ASTR + acol + j] = f2tf32(av[j] - __uint_as_float(hi));
        }
    }
    CP_WAIT0();
    __syncthreads();

    float acc[2][8][4];
#pragma unroll
    for (int mi = 0; mi < 2; mi++)
#pragma unroll
        for (int ni = 0; ni < 8; ni++)
#pragma unroll
            for (int q = 0; q < 4; q++) acc[mi][ni][q] = 0.f;

    const int nk = K >> 3;
    int buf = 0;
    for (int kt = 0; kt < nk; kt++) {
        const int nb = buf ^ 1;
        if (kt + 1 < nk) {
            int kb = (kt + 1) << 3;
            cp_async16(smem_u32(&Bs_h[nb][brow * BSTR + bcol]), BptrH + (size_t)kb * Nc);
            cp_async16(smem_u32(&Bs_l[nb][brow * BSTR + bcol]), BptrL + (size_t)kb * Nc);
            CP_COMMIT();
            ap = aval ? *reinterpret_cast<const float4*>(Aptr + kb)
                      : make_float4(0.f, 0.f, 0.f, 0.f);
        }
        uint32_t ah[2][4], al[2][4];
#pragma unroll
        for (int mi = 0; mi < 2; mi++) {
            int mbase = wm + mi * 16;
#pragma unroll
            for (int q = 0; q < 4; q++) {
                int r = mbase + g + (q & 1) * 8;
                int c = ct + (q >> 1) * 4;
                ah[mi][q] = As_h[buf][r * ASTR + c];
                al[mi][q] = As_l[buf][r * ASTR + c];
            }
        }
#pragma unroll
        for (int ni = 0; ni < 8; ni++) {
            int nbase = wn + ni * 8 + g;
            uint32_t bh0 = Bs_h[buf][ct * BSTR + nbase];
            uint32_t bh1 = Bs_h[buf][(ct + 4) * BSTR + nbase];
            uint32_t bl0 = Bs_l[buf][ct * BSTR + nbase];
            uint32_t bl1 = Bs_l[buf][(ct + 4) * BSTR + nbase];
#pragma unroll
            for (int mi = 0; mi < 2; mi++) {
                mma_tf32(acc[mi][ni], ah[mi], bl0, bl1);   // Ah*Bl
                mma_tf32(acc[mi][ni], al[mi], bh0, bh1);   // Al*Bh
                mma_tf32(acc[mi][ni], ah[mi], bh0, bh1);   // Ah*Bh
            }
        }
        if (kt + 1 < nk) {
            float av[4] = {ap.x, ap.y, ap.z, ap.w};
#pragma unroll
            for (int j = 0; j < 4; j++) {
                uint32_t hi = f2tf32(av[j]);
                As_h[nb][arow * ASTR + acol + j] = hi;
                As_l[nb][arow * ASTR + acol + j] = f2tf32(av[j] - __uint_as_float(hi));
            }
            CP_WAIT0();
        }
        __syncthreads();
        buf ^= 1;
    }

    float aggsc = 0.f;
    if (agg_out) aggsc = 1.f + __ldg(eps + next_l);
#pragma unroll
    for (int mi = 0; mi < 2; mi++) {
#pragma unroll
        for (int half = 0; half < 2; half++) {
            int r = m0 + wm + mi * 16 + g + half * 8;
            if (r >= M) continue;
#pragma unroll
            for (int ni = 0; ni < 8; ni++) {
                int cix = n0 + wn + ni * 8 + ct * 2;
                float v0 = acc[mi][ni][half * 2 + 0];
                float v1 = acc[mi][ni][half * 2 + 1];
                if (mode == 0) {
                    float sc0 = gamma[cix + 0] * rsqrtf(var[cix + 0] + BN_EPS);
                    float sc1 = gamma[cix + 1] * rsqrtf(var[cix + 1] + BN_EPS);
                    v0 = fmaxf((v0 + bias[cix + 0] - mean[cix + 0]) * sc0 + beta[cix + 0], 0.f);
                    v1 = fmaxf((v1 + bias[cix + 1] - mean[cix + 1]) * sc1 + beta[cix + 1], 0.f);
                } else if (mode == 1) {
                    v0 += bias[cix + 0];
                    v1 += bias[cix + 1];
                } else {
                    v0 = tanhf(v0 + bias[cix + 0]);
                    v1 = tanhf(v1 + bias[cix + 1]);
                }
                *reinterpret_cast<float2*>(C + (size_t)r * Nc + cix) = make_float2(v0, v1);
                if (agg_out) {
                    *reinterpret_cast<float2*>(agg_out + (size_t)r * Nc + cix) =
                        make_float2(v0 * aggsc, v1 * aggsc);
                }
            }
        }
    }
}

// ---------------- remaining pipeline (unchanged, proven) ----------------

__global__ __launch_bounds__(256) void assign_pool(const float* __restrict__ c2W,
                                                   const float* __restrict__ c2b,
                                                   const int* __restrict__ batch,
                                                   float* __restrict__ out) {
    int n = blockIdx.x;
    int c = threadIdx.x;
    float t = g_agg[(size_t)n * HH + c];
    float2 lg = block_reduce2(t * c2W[c * 2 + 0], t * c2W[c * 2 + 1]);
    float l0 = lg.x + c2b[0], l1 = lg.y + c2b[1];
    float m = fmaxf(l0, l1);
    float e0 = expf(l0 - m), e1 = expf(l1 - m);
    float inv = 1.f / (e0 + e1);
    float a0 = e0 * inv, a1 = e1 * inv;
    float hv = g_h[(size_t)n * HH + c];
    int g = batch[n];
    atomicAdd(&g_sub[g * HH + c], a0 * hv);
    atomicAdd(&g_triv[g * HH + c], a1 * hv);
    atomicAdd(&g_gsum[g * HH + c], hv);
    if (c == 0) {
        atomicAdd(&g_cnt[g], 1.f);
        out[O_MASK + n] = (a0 > 0.5f) ? 1.f : 0.f;
        g_assign[(size_t)n * 2 + 0] = a0;
        g_assign[(size_t)n * 2 + 1] = a1;
    }
}

__global__ __launch_bounds__(256) void adj_k(const int* __restrict__ ei,
                                             const int* __restrict__ batch) {
    int e = blockIdx.x * 256 + threadIdx.x;
    if (e >= EE) return;
    int s = ei[e], d = ei[EE + e];
    int gs = batch[s], gd = batch[d];
    if (gs != gd) return;
    float as0 = g_assign[(size_t)s * 2], as1 = g_assign[(size_t)s * 2 + 1];
    float ad0 = g_assign[(size_t)d * 2], ad1 = g_assign[(size_t)d * 2 + 1];
    float* A = g_adj + gs * 4;
    atomicAdd(A + 0, as0 * ad0);
    atomicAdd(A + 1, as0 * ad1);
    atomicAdd(A + 2, as1 * ad0);
    atomicAdd(A + 3, as1 * ad1);
}

__global__ __launch_bounds__(256) void fin_pool(float* __restrict__ out) {
    int i = blockIdx.x * 256 + threadIdx.x;
    if (i >= GG * HH) return;
    int g = i / HH;
    out[O_SUB + i] = g_sub[i];
    out[O_GE + i] = g_gsum[i] / fmaxf(g_cnt[g], 1.f);
}

__global__ __launch_bounds__(256) void head_k(int which,
                                              const float* __restrict__ l1W,
                                              const float* __restrict__ l1b,
                                              const float* __restrict__ l2W,
                                              const float* __restrict__ l2b,
                                              float* __restrict__ out) {
    int g = blockIdx.x;
    int c = threadIdx.x;
    __shared__ float row[HH];
    row[c] = (which == 0) ? g_sub[(size_t)g * HH + c] : g_triv[(size_t)g * HH + c];
    __syncthreads();
    float acc = l1b[c];
#pragma unroll 4
    for (int k = 0; k < HH; k++)
        acc += row[k] * l1W[(size_t)k * HH + c];
    float z = fmaxf(acc, 0.f);
    float2 lg = block_reduce2(z * l2W[c * 2 + 0], z * l2W[c * 2 + 1]);
    if (c == 0) {
        float l0 = lg.x + l2b[0], l1 = lg.y + l2b[1];
        float m = fmaxf(l0, l1);
        float ls = logf(expf(l0 - m) + expf(l1 - m)) + m;
        out[g * 2 + 0] = l0 - ls;
        out[g * 2 + 1] = l1 - ls;
    }
}

__global__ __launch_bounds__(256) void pen_k() {
    int g = blockIdx.x * 256 + threadIdx.x;
    if (g >= GG) return;
    float a00 = g_adj[g * 4 + 0], a01 = g_adj[g * 4 + 1];
    float a10 = g_adj[g * 4 + 2], a11 = g_adj[g * 4 + 3];
    float r0 = fmaxf(fabsf(a00) + fabsf(a01), 1e-12f);
    float r1 = fmaxf(fabsf(a10) + fabsf(a11), 1e-12f);
    float d0 = a00 / r0 - 1.f, d1 = a11 / r1 - 1.f;
    atomicAdd(g_pen, d0 * d0 + d1 * d1);
}

__global__ void pen_w(float* __restrict__ out) {
    out[O_PEN] = g_pen[0] / (2.f * GG);
}

// ---------------- host launcher ----------------
extern "C" void kernel_launch(void* const* d_in, const int* in_sizes, int n_in,
                              void* d_out, int out_size) {
    int o = (n_in >= 24) ? 1 : 0;
    const int*   x     = (const int*)d_in[0];
    const int*   ei    = (const int*)d_in[1];
    const int*   ea    = (const int*)d_in[2];
    const int*   batch = (const int*)d_in[3];
    const float* aemb  = (const float*)d_in[4 + o];
    const float* bemb  = (const float*)d_in[5 + o];
    const float* eps   = (const float*)d_in[6 + o];
    const float* W1    = (const float*)d_in[7 + o];
    const float* b1    = (const float*)d_in[8 + o];
    const float* gma   = (const float*)d_in[9 + o];
    const float* bta   = (const float*)d_in[10 + o];
    const float* mu    = (const float*)d_in[11 + o];
    const float* var   = (const float*)d_in[12 + o];
    const float* W2    = (const float*)d_in[13 + o];
    const float* b2    = (const float*)d_in[14 + o];
    const float* c1W   = (const float*)d_in[15 + o];
    const float* c1b   = (const float*)d_in[16 + o];
    const float* c2W   = (const float*)d_in[17 + o];
    const float* c2b   = (const float*)d_in[18 + o];
    const float* l1W   = (const float*)d_in[19 + o];
    const float* l1b   = (const float*)d_in[20 + o];
    const float* l2W   = (const float*)d_in[21 + o];
    const float* l2b   = (const float*)d_in[22 + o];
    float* out = (float*)d_out;

    float *p_h, *p_agg, *p_z;
    uint32_t *p_wh, *p_wl;
    cudaGetSymbolAddress((void**)&p_h, g_h);
    cudaGetSymbolAddress((void**)&p_agg, g_agg);
    cudaGetSymbolAddress((void**)&p_z, g_z);
    cudaGetSymbolAddress((void**)&p_wh, g_wh);
    cudaGetSymbolAddress((void**)&p_wl, g_wl);

    zero_k<<<(GG * HH + 255) / 256, 256>>>();
    atom_enc<<<NN, 256>>>(x, aemb, eps);
    bsum_k<<<dim3(NCOMBO, LLAY), 256>>>(bemb);

    // pre-split weights (static per launch): W[K][N] -> tf32 hi/lo, same layout
    for (int l = 0; l < LLAY; l++) {
        wsplit<<<dim3(2, HH), 256>>>(W1 + (size_t)l * HH * H2,
                                     p_wh + WOFF_W1(l), p_wl + WOFF_W1(l), H2);
        wsplit<<<dim3(1, H2), 256>>>(W2 + (size_t)l * H2 * HH,
                                     p_wh + WOFF_W2(l), p_wl + WOFF_W2(l), HH);
    }
    wsplit<<<dim3(1, HH), 256>>>(c1W, p_wh + WOFF_C1, p_wl + WOFF_C1, HH);

    const int gmx = (NN + 127) / 128;
    for (int l = 0; l < LLAY; l++) {
        edge_msg<<<(EE + 7) / 8, 256>>>(ei, ea, l);
        // z = relu(BN(agg @ W1[l] + b1[l]))   [N, 512]
        mma_gemm<<<dim3(gmx, H2 / 128), 256>>>(p_agg,
                                               p_wh + WOFF_W1(l), p_wl + WOFF_W1(l),
                                               p_z, NN, HH, H2, 0,
                                               b1 + (size_t)l * H2, gma + (size_t)l * H2,
                                               bta + (size_t)l * H2, mu + (size_t)l * H2,
                                               var + (size_t)l * H2,
                                               nullptr, 0, nullptr);
        // h = z @ W2[l] + b2[l]               [N, 256]; fused agg init for next layer
        float* next_agg = (l + 1 < LLAY) ? p_agg : nullptr;
        mma_gemm<<<dim3(gmx, HH / 128), 256>>>(p_z,
                                               p_wh + WOFF_W2(l), p_wl + WOFF_W2(l),
                                               p_h, NN, H2, HH, 1,
                                               b2 + (size_t)l * HH, nullptr, nullptr,
                                               nullptr, nullptr,
                                               eps, l + 1, next_agg);
    }

    // t = tanh(h @ c1W + c1b)  -> g_agg
    mma_gemm<<<dim3(gmx, HH / 128), 256>>>(p_h,
                                           p_wh + WOFF_C1, p_wl + WOFF_C1,
                                           p_agg, NN, HH, HH, 2,
                                           c1b, nullptr, nullptr, nullptr, nullptr,
                                           nullptr, 0, nullptr);

    assign_pool<<<NN, 256>>>(c2W, c2b, batch, out);
    adj_k<<<(EE + 255) / 256, 256>>>(ei, batch);
    fin_pool<<<(GG * HH + 255) / 256, 256>>>(out);
    head_k<<<GG, 256>>>(0, l1W, l1b, l2W, l2b, out + O_HS);
    head_k<<<GG, 256>>>(1, l1W, l1b, l2W, l2b, out + O_HT);
    pen_k<<<(GG + 255) / 256, 256>>>();
    pen_w<<<1, 1>>>(out);
    (void)in_sizes; (void)out_size;
}